// round 3
// baseline (speedup 1.0000x reference)
#include <cuda_runtime.h>
#include <cstdint>

// Problem constants (fixed shapes from reference)
#define M_DIM 8192   // TOK
#define N_DIM 4096   // OUT
#define K_DIM 4096   // IN
#define GRP   16

#define BM 128
#define BN 128
#define BK 32
#define AST (BK + 4)          // padded row stride (floats)
#define NTHREADS 256

__device__ __forceinline__ float to_tf32(float x) {
    uint32_t o;
    asm volatile("cvt.rna.tf32.f32 %0, %1;\n" : "=r"(o) : "f"(x));
    return __uint_as_float(o);
}

__device__ __forceinline__ void mma_tf32(float c[4], const float a[4], const float b[2]) {
    const uint32_t* A = reinterpret_cast<const uint32_t*>(a);
    const uint32_t* B = reinterpret_cast<const uint32_t*>(b);
    asm volatile(
        "mma.sync.aligned.m16n8k8.row.col.f32.tf32.tf32.f32 "
        "{%0,%1,%2,%3}, {%4,%5,%6,%7}, {%8,%9}, {%0,%1,%2,%3};\n"
        : "+f"(c[0]), "+f"(c[1]), "+f"(c[2]), "+f"(c[3])
        : "r"(A[0]), "r"(A[1]), "r"(A[2]), "r"(A[3]), "r"(B[0]), "r"(B[1]));
}

__global__ void __launch_bounds__(NTHREADS)
linear4bit_tf32_kernel(const float* __restrict__ X,
                       const int*   __restrict__ Wq,    // one byte (2 nibbles) per int32
                       const float* __restrict__ Wn,    // [N*K/16] group norms (fp16 widened to fp32)
                       const float* __restrict__ bias,  // [N]
                       float* __restrict__ Y)           // [M, N]
{
    const int bm = blockIdx.y * BM;
    const int bn = blockIdx.x * BN;
    const int tid = threadIdx.x;
    const int warp = tid >> 5;
    const int lane = tid & 31;
    const int lg = lane >> 2;   // groupID (0..7)
    const int lq = lane & 3;    // threadID_in_group (0..3)
    const int wm = (warp >> 1) * 32;  // warp M offset within block tile
    const int wn = (warp & 1) * 64;   // warp N offset within block tile

    extern __shared__ float smem[];
    float* As = smem;                       // [2][BM*AST]
    float* Bs = smem + 2 * BM * AST;        // [2][BN*AST]

    float c[2][8][4];
    #pragma unroll
    for (int mi = 0; mi < 2; ++mi)
        #pragma unroll
        for (int ni = 0; ni < 8; ++ni)
            #pragma unroll
            for (int j = 0; j < 4; ++j) c[mi][ni][j] = 0.0f;

    // --- B (weights) register prefetch state ---
    const int r0 = tid >> 2;   // 0..63   (n row within half-tile)
    const int q4 = tid & 3;    // which 8-k chunk of the 32-k slice
    int4  breg[2];
    float bnorm[2];

    // ---- loaders ----
    auto load_a_async = [&](int k0, int buf) {
        float* as = As + buf * BM * AST;
        #pragma unroll
        for (int j = 0; j < 4; ++j) {
            int f = tid + j * NTHREADS;
            int row = f >> 3, seg = f & 7;
            const float* g = X + (size_t)(bm + row) * K_DIM + k0 + seg * 4;
            uint32_t sa = (uint32_t)__cvta_generic_to_shared(as + row * AST + seg * 4);
            asm volatile("cp.async.cg.shared.global [%0], [%1], 16;\n" :: "r"(sa), "l"(g));
        }
        asm volatile("cp.async.commit_group;\n");
    };

    auto load_b_regs = [&](int k0) {
        #pragma unroll
        for (int u = 0; u < 2; ++u) {
            int n = bn + r0 + u * 64;
            // int32 element index for weight k of row n is n*(K/2) + k/2.
            const int* rp = Wq + (size_t)n * (K_DIM / 2) + (k0 >> 1);
            breg[u] = reinterpret_cast<const int4*>(rp)[q4];    // weights k0+q4*8 .. +7
            bnorm[u] = Wn[(size_t)n * (K_DIM / GRP) + (k0 >> 4) + (q4 >> 1)];
        }
    };

    auto store_b = [&](int buf) {
        float* bs = Bs + buf * BN * AST;
        #pragma unroll
        for (int u = 0; u < 2; ++u) {
            float nf = bnorm[u];
            float s = nf * (2.0f / 15.0f);
            int v[4] = {breg[u].x, breg[u].y, breg[u].z, breg[u].w};
            float o[8];
            #pragma unroll
            for (int j = 0; j < 4; ++j) {
                o[2 * j]     = to_tf32((float)(v[j] & 15)        * s - nf);  // low nibble = even k
                o[2 * j + 1] = to_tf32((float)((v[j] >> 4) & 15) * s - nf);  // high nibble = odd k
            }
            float4* dst = reinterpret_cast<float4*>(bs + (r0 + u * 64) * AST + q4 * 8);
            dst[0] = make_float4(o[0], o[1], o[2], o[3]);
            dst[1] = make_float4(o[4], o[5], o[6], o[7]);
        }
    };

    auto compute = [&](int buf) {
        const float* as = As + buf * BM * AST;
        const float* bs = Bs + buf * BN * AST;
        #pragma unroll
        for (int ks = 0; ks < 4; ++ks) {
            const int col = ks * 8 + lq;   // PTX tf32 m16n8k8: cols are lq and lq+4
            float a[2][4];
            float b[8][2];
            #pragma unroll
            for (int mi = 0; mi < 2; ++mi) {
                int r = wm + mi * 16 + lg;
                a[mi][0] = to_tf32(as[r * AST + col]);            // (m,   lq)
                a[mi][1] = to_tf32(as[(r + 8) * AST + col]);      // (m+8, lq)
                a[mi][2] = to_tf32(as[r * AST + col + 4]);        // (m,   lq+4)
                a[mi][3] = to_tf32(as[(r + 8) * AST + col + 4]);  // (m+8, lq+4)
            }
            #pragma unroll
            for (int ni = 0; ni < 8; ++ni) {
                int n = wn + ni * 8 + lg;
                b[ni][0] = bs[n * AST + col];                     // (k=lq,   n)
                b[ni][1] = bs[n * AST + col + 4];                 // (k=lq+4, n)
            }
            #pragma unroll
            for (int mi = 0; mi < 2; ++mi)
                #pragma unroll
                for (int ni = 0; ni < 8; ++ni)
                    mma_tf32(c[mi][ni], a[mi], b[ni]);
        }
    };

    // ---- prologue: stage 0 ----
    load_a_async(0, 0);
    load_b_regs(0);
    asm volatile("cp.async.wait_group 0;\n");
    store_b(0);
    __syncthreads();

    const int NK = K_DIM / BK;  // 128 iterations
    for (int it = 0; it < NK; ++it) {
        int buf = it & 1;
        int nbuf = buf ^ 1;
        if (it + 1 < NK) {
            load_a_async((it + 1) * BK, nbuf);
            load_b_regs((it + 1) * BK);
        }
        compute(buf);
        if (it + 1 < NK) {
            asm volatile("cp.async.wait_group 0;\n");
            store_b(nbuf);
        }
        __syncthreads();
    }

    // ---- epilogue: bias + store fp32 ----
    #pragma unroll
    for (int ni = 0; ni < 8; ++ni) {
        int coln = bn + wn + ni * 8 + 2 * lq;
        float2 bv = *reinterpret_cast<const float2*>(bias + coln);
        #pragma unroll
        for (int mi = 0; mi < 2; ++mi) {
            int r = bm + wm + mi * 16 + lg;
            float2 v0 = make_float2(c[mi][ni][0] + bv.x, c[mi][ni][1] + bv.y);
            float2 v1 = make_float2(c[mi][ni][2] + bv.x, c[mi][ni][3] + bv.y);
            *reinterpret_cast<float2*>(Y + (size_t)r * N_DIM + coln) = v0;
            *reinterpret_cast<float2*>(Y + (size_t)(r + 8) * N_DIM + coln) = v1;
        }
    }
}

extern "C" void kernel_launch(void* const* d_in, const int* in_sizes, int n_in,
                              void* d_out, int out_size) {
    const float* X    = (const float*)d_in[0];
    const int*   Wq   = (const int*)d_in[1];
    const float* Wn   = (const float*)d_in[2];   // fp16 widened to fp32 by harness
    const float* bias = (const float*)d_in[3];
    float*       Y    = (float*)d_out;

    const int smem_bytes = (2 * BM * AST + 2 * BN * AST) * (int)sizeof(float); // 73728
    cudaFuncSetAttribute(linear4bit_tf32_kernel,
                         cudaFuncAttributeMaxDynamicSharedMemorySize, smem_bytes);

    dim3 grid(N_DIM / BN, M_DIM / BM);  // (32, 64)
    linear4bit_tf32_kernel<<<grid, NTHREADS, smem_bytes>>>(X, Wq, Wn, bias, Y);
}